// round 2
// baseline (speedup 1.0000x reference)
#include <cuda_runtime.h>

#define NN 100000
#define NE 1600000
#define NG 512
#define FIN 20
#define H 128
#define FOUT 64

// ---------------- scratch (static device globals; no allocs) ----------------
__device__ __align__(128) float g_deg[NN];
__device__ __align__(128) float g_dinv[NN];
__device__ __align__(128) float g_y20[NN * FIN];
__device__ __align__(128) float g_a20[NN * FIN];
__device__ __align__(128) float g_Y[(size_t)NN * H];
__device__ __align__(128) float g_A[(size_t)NN * H];
__device__ __align__(128) float g_pool[NG * H];
__device__ __align__(128) float g_cnt[NG];

// ---------------- helpers ----------------
__device__ __forceinline__ unsigned long long pk2(float lo, float hi) {
    unsigned long long r;
    asm("mov.b64 %0,{%1,%2};" : "=l"(r) : "f"(lo), "f"(hi));
    return r;
}
__device__ __forceinline__ void fma2(unsigned long long& d, unsigned long long a, unsigned long long b) {
    asm("fma.rn.f32x2 %0,%1,%2,%0;" : "+l"(d) : "l"(a), "l"(b));
}
__device__ __forceinline__ void unpk2(unsigned long long v, float& lo, float& hi) {
    asm("mov.b64 {%0,%1},%2;" : "=f"(lo), "=f"(hi) : "l"(v));
}
__device__ __forceinline__ void red4(float* p, float a, float b, float c, float d) {
    asm volatile("red.global.add.v4.f32 [%0],{%1,%2,%3,%4};"
                 :: "l"(p), "f"(a), "f"(b), "f"(c), "f"(d) : "memory");
}

// ---------------- small kernels ----------------
__global__ void k_zero() {
    int i = blockIdx.x * blockDim.x + threadIdx.x;
    if (i < NN) g_deg[i] = 0.f;
    if (i < NG * H) g_pool[i] = 0.f;
    if (i < NG) g_cnt[i] = 0.f;
}

__global__ void k_deg(const int* __restrict__ ei) {
    int e = blockIdx.x * blockDim.x + threadIdx.x;
    if (e < NE) atomicAdd(&g_deg[ei[NE + e]], 1.0f);
}

__global__ void k_dinv() {
    int i = blockIdx.x * blockDim.x + threadIdx.x;
    if (i < NN) g_dinv[i] = rsqrtf(g_deg[i] + 1.0f);  // +1 = self loop
}

__global__ void k_cnt(const int* __restrict__ batch) {
    int i = blockIdx.x * blockDim.x + threadIdx.x;
    if (i < NN) atomicAdd(&g_cnt[batch[i]], 1.0f);
}

// y20 = x * dinv (per-row);  a20 init = y20 (self-loop term)
__global__ void k_init20(const float* __restrict__ x) {
    int t = blockIdx.x * blockDim.x + threadIdx.x;
    if (t >= NN * 5) return;
    int i = t / 5, q = t % 5;
    float s = g_dinv[i];
    float4 v = *(const float4*)(x + i * FIN + q * 4);
    v.x *= s; v.y *= s; v.z *= s; v.w *= s;
    *(float4*)(g_y20 + i * FIN + q * 4) = v;
    *(float4*)(g_a20 + i * FIN + q * 4) = v;
}

// a20[dst] += y20[src]   (20-dim, 5 threads/edge)
__global__ void k_edge20(const int* __restrict__ ei) {
    int t = blockIdx.x * blockDim.x + threadIdx.x;
    if (t >= NE * 5) return;
    int e = t / 5, q = t % 5;
    int s = __ldg(ei + e);
    int d = __ldg(ei + NE + e);
    float4 v = __ldg((const float4*)(g_y20 + (size_t)s * FIN) + q);
    red4(g_a20 + (size_t)d * FIN + q * 4, v.x, v.y, v.z, v.w);
}

// g_A[dst] += g_Y[src]   (128-dim, one warp per edge, 32x float4 red)
__global__ void k_edge128(const int* __restrict__ ei) {
    int t = blockIdx.x * blockDim.x + threadIdx.x;
    int e = t >> 5;
    if (e >= NE) return;
    int lane = t & 31;
    int s = __ldg(ei + e);
    int d = __ldg(ei + NE + e);
    float4 v = __ldg((const float4*)(g_Y + (size_t)s * H) + lane);
    red4(g_A + (size_t)d * H + lane * 4, v.x, v.y, v.z, v.w);
}

// ---------------- fused GEMM ----------------
// out_row = relu( (dinv[row] * A[row,:]) @ W + b )
// MODE 0: store out*dinv[row] into both g_Y and g_A (prep for next aggregation)
// MODE 1: red.v4-accumulate out into g_pool[batch[row]]   (final layer)
// SRC via K: K==FIN reads g_a20, else g_A.
template <int K, int KC, int KCP, int MODE>
__global__ __launch_bounds__(256) void k_gemm(const float* __restrict__ W,
                                              const float* __restrict__ bias,
                                              const int* __restrict__ batch) {
    const float* A = (K == FIN) ? (const float*)g_a20 : (const float*)g_A;
    __shared__ float Ws[KC * H];
    __shared__ float As[64 * KCP];
    int tid = threadIdx.x;
    int row0 = blockIdx.x * 64;
    int rg = tid >> 4;        // 0..15 -> rows rg*4 .. rg*4+3
    int cg = tid & 15;        // 0..15 -> cols cg*8 .. cg*8+7
    int c0 = cg * 8;

    unsigned long long acc[4][4];
#pragma unroll
    for (int r = 0; r < 4; r++)
#pragma unroll
        for (int j = 0; j < 4; j++) acc[r][j] = 0ull;

    for (int kc = 0; kc < K; kc += KC) {
        // stage W tile [KC x 128]
        for (int t = tid; t < KC * 32; t += 256) {
            int kk = t >> 5, c4 = (t & 31) * 4;
            *(float4*)(Ws + kk * H + c4) = *(const float4*)(W + (size_t)(kc + kk) * H + c4);
        }
        // stage A tile [64 x KC], scaled by dinv
        for (int t = tid; t < (64 * KC) / 4; t += 256) {
            int r = t / (KC / 4), q = (t % (KC / 4)) * 4;
            int row = row0 + r;
            float4 v = make_float4(0.f, 0.f, 0.f, 0.f);
            float s = 0.f;
            if (row < NN) {
                v = *(const float4*)(A + (size_t)row * K + kc + q);
                s = g_dinv[row];
            }
            v.x *= s; v.y *= s; v.z *= s; v.w *= s;
            *(float4*)(As + r * KCP + q) = v;
        }
        __syncthreads();
#pragma unroll
        for (int kk = 0; kk < KC; kk++) {
            ulonglong2 w0 = *(const ulonglong2*)(Ws + kk * H + c0);
            ulonglong2 w1 = *(const ulonglong2*)(Ws + kk * H + c0 + 4);
#pragma unroll
            for (int r = 0; r < 4; r++) {
                float a = As[(rg * 4 + r) * KCP + kk];
                unsigned long long aa = pk2(a, a);
                fma2(acc[r][0], aa, w0.x);
                fma2(acc[r][1], aa, w0.y);
                fma2(acc[r][2], aa, w1.x);
                fma2(acc[r][3], aa, w1.y);
            }
        }
        __syncthreads();
    }

    float b[8];
#pragma unroll
    for (int c = 0; c < 8; c++) b[c] = __ldg(bias + c0 + c);

#pragma unroll
    for (int r = 0; r < 4; r++) {
        int row = row0 + rg * 4 + r;
        if (row >= NN) continue;
        float o[8];
#pragma unroll
        for (int j = 0; j < 4; j++) unpk2(acc[r][j], o[2 * j], o[2 * j + 1]);
#pragma unroll
        for (int c = 0; c < 8; c++) o[c] = fmaxf(o[c] + b[c], 0.f);

        if (MODE == 0) {
            float s = g_dinv[row];
            float4 v0 = make_float4(o[0] * s, o[1] * s, o[2] * s, o[3] * s);
            float4 v1 = make_float4(o[4] * s, o[5] * s, o[6] * s, o[7] * s);
            size_t base = (size_t)row * H + c0;
            *(float4*)(g_Y + base) = v0;
            *(float4*)(g_Y + base + 4) = v1;
            *(float4*)(g_A + base) = v0;
            *(float4*)(g_A + base + 4) = v1;
        } else {
            int g = __ldg(batch + row);
            float* p = g_pool + (size_t)g * H + c0;
            red4(p, o[0], o[1], o[2], o[3]);
            red4(p + 4, o[4], o[5], o[6], o[7]);
        }
    }
}

// out[g, c] = (pool[g,:] @ Wout[:,c]) / max(cnt[g],1) + bout[c]
__global__ void k_final(const float* __restrict__ Wout,
                        const float* __restrict__ bout,
                        float* __restrict__ out) {
    int g = blockIdx.x;
    int c = threadIdx.x;  // 0..63
    float inv = 1.0f / fmaxf(g_cnt[g], 1.0f);
    float acc = 0.f;
#pragma unroll 16
    for (int k = 0; k < H; k++)
        acc += g_pool[g * H + k] * __ldg(Wout + k * FOUT + c);
    out[g * FOUT + c] = acc * inv + bout[c];
}

// ---------------- launch ----------------
extern "C" void kernel_launch(void* const* d_in, const int* in_sizes, int n_in,
                              void* d_out, int out_size) {
    const float* x = (const float*)d_in[0];
    const int* ei = (const int*)d_in[1];     // [2, NE] int32 (JAX x64 disabled)
    const int* batch = (const int*)d_in[2];  // [NN] int32
    const float* W1 = (const float*)d_in[3];
    const float* b1 = (const float*)d_in[4];
    const float* W2 = (const float*)d_in[5];
    const float* b2 = (const float*)d_in[6];
    const float* W3 = (const float*)d_in[7];
    const float* b3 = (const float*)d_in[8];
    const float* Wo = (const float*)d_in[9];
    const float* bo = (const float*)d_in[10];
    float* out = (float*)d_out;

    const int gemm_blocks = (NN + 63) / 64;
    const int edge128_blocks = (int)(((size_t)NE * 32 + 255) / 256);

    k_zero<<<(NN + 255) / 256, 256>>>();
    k_deg<<<(NE + 255) / 256, 256>>>(ei);
    k_dinv<<<(NN + 255) / 256, 256>>>();
    k_cnt<<<(NN + 255) / 256, 256>>>(batch);

    // layer 1: aggregate 20-dim input, then GEMM 20->128
    k_init20<<<(NN * 5 + 255) / 256, 256>>>(x);
    k_edge20<<<(NE * 5 + 255) / 256, 256>>>(ei);
    k_gemm<FIN, 20, 24, 0><<<gemm_blocks, 256>>>(W1, b1, nullptr);

    // layer 2
    k_edge128<<<edge128_blocks, 256>>>(ei);
    k_gemm<H, 32, 36, 0><<<gemm_blocks, 256>>>(W2, b2, nullptr);

    // layer 3 (epilogue pools directly)
    k_edge128<<<edge128_blocks, 256>>>(ei);
    k_gemm<H, 32, 36, 1><<<gemm_blocks, 256>>>(W3, b3, batch);

    // head
    k_final<<<NG, FOUT>>>(Wo, bo, out);
}

// round 6
// speedup vs baseline: 1.5248x; 1.5248x over previous
#include <cuda_runtime.h>

#define NN 100000
#define NE 1600000
#define NG 512
#define FIN 20
#define H 128
#define FOUT 64
#define NBS ((NN + 255) / 256)   // scan blocks = 391

// ---------------- scratch (static device globals; no allocs) ----------------
__device__ __align__(128) int   g_degi[NN];
__device__ __align__(128) int   g_off[NN];
__device__ __align__(128) int   g_cur[NN];
__device__ __align__(128) int   g_bsum[NBS];
__device__ __align__(128) int   g_bpre[NBS];
__device__ __align__(128) int   g_adj[NE];
__device__ __align__(128) float g_dinv[NN];
__device__ __align__(128) float g_y20[NN * FIN];
__device__ __align__(128) float g_a20[NN * FIN];
__device__ __align__(128) float g_Y[(size_t)NN * H];
__device__ __align__(128) float g_A[(size_t)NN * H];
__device__ __align__(128) float g_pool[NG * H];
__device__ __align__(128) float g_cnt[NG];

// ---------------- helpers ----------------
__device__ __forceinline__ unsigned long long pk2(float lo, float hi) {
    unsigned long long r;
    asm("mov.b64 %0,{%1,%2};" : "=l"(r) : "f"(lo), "f"(hi));
    return r;
}
__device__ __forceinline__ void fma2(unsigned long long& d, unsigned long long a, unsigned long long b) {
    asm("fma.rn.f32x2 %0,%1,%2,%0;" : "+l"(d) : "l"(a), "l"(b));
}
__device__ __forceinline__ void unpk2(unsigned long long v, float& lo, float& hi) {
    asm("mov.b64 {%0,%1},%2;" : "=f"(lo), "=f"(hi) : "l"(v));
}
__device__ __forceinline__ void red4(float* p, float a, float b, float c, float d) {
    asm volatile("red.global.add.v4.f32 [%0],{%1,%2,%3,%4};"
                 :: "l"(p), "f"(a), "f"(b), "f"(c), "f"(d) : "memory");
}

// ---------------- setup kernels ----------------
__global__ void k_zero() {
    int i = blockIdx.x * blockDim.x + threadIdx.x;
    if (i < NN) { g_degi[i] = 0; g_cur[i] = 0; }
    if (i < NG * H) g_pool[i] = 0.f;
    if (i < NG) g_cnt[i] = 0.f;
}

__global__ void k_deg(const int* __restrict__ ei) {
    int e = blockIdx.x * blockDim.x + threadIdx.x;
    if (e < NE) atomicAdd(&g_degi[__ldg(ei + NE + e)], 1);
}

// smem-aggregated graph-size histogram (batch is sorted -> few bins per block)
__global__ void k_cnt(const int* __restrict__ batch) {
    __shared__ float h[NG];
    for (int g = threadIdx.x; g < NG; g += 256) h[g] = 0.f;
    __syncthreads();
    int i = blockIdx.x * blockDim.x + threadIdx.x;
    if (i < NN) atomicAdd(&h[__ldg(batch + i)], 1.0f);
    __syncthreads();
    for (int g = threadIdx.x; g < NG; g += 256)
        if (h[g] != 0.f) atomicAdd(&g_cnt[g], h[g]);
}

// ---------------- exclusive scan of g_degi -> g_off (3 kernels) ----------------
__global__ void k_scan1() {
    __shared__ int s[2][256];
    int t = threadIdx.x, b = blockIdx.x;
    int i = b * 256 + t;
    int v = (i < NN) ? g_degi[i] : 0;
    int cur = 0;
    s[0][t] = v;
    __syncthreads();
#pragma unroll
    for (int o = 1; o < 256; o <<= 1) {
        int nv = s[cur][t] + (t >= o ? s[cur][t - o] : 0);
        s[cur ^ 1][t] = nv;
        __syncthreads();
        cur ^= 1;
    }
    int inc = s[cur][t];
    if (i < NN) g_off[i] = inc - v;      // block-local exclusive
    if (t == 255) g_bsum[b] = inc;
}

__global__ void k_scan2() {
    __shared__ int s[2][512];
    int t = threadIdx.x;
    int v = (t < NBS) ? g_bsum[t] : 0;
    int cur = 0;
    s[0][t] = v;
    __syncthreads();
#pragma unroll
    for (int o = 1; o < 512; o <<= 1) {
        int nv = s[cur][t] + (t >= o ? s[cur][t - o] : 0);
        s[cur ^ 1][t] = nv;
        __syncthreads();
        cur ^= 1;
    }
    if (t < NBS) g_bpre[t] = s[cur][t] - v;   // exclusive
}

__global__ void k_scan3() {
    int i = blockIdx.x * blockDim.x + threadIdx.x;
    if (i < NN) {
        g_off[i] += g_bpre[i >> 8];
        g_dinv[i] = rsqrtf((float)g_degi[i] + 1.0f);  // +1 = self loop
    }
}

// fill CSR adjacency: g_adj[off[d] .. off[d]+deg[d]) = src of edges into d
__global__ void k_scatter(const int* __restrict__ ei) {
    int e = blockIdx.x * blockDim.x + threadIdx.x;
    if (e >= NE) return;
    int s = __ldg(ei + e);
    int d = __ldg(ei + NE + e);
    int pos = g_off[d] + atomicAdd(&g_cur[d], 1);
    g_adj[pos] = s;
}

// ---------------- layer-1 feature prep ----------------
__global__ void k_init20(const float* __restrict__ x) {
    int t = blockIdx.x * blockDim.x + threadIdx.x;
    if (t >= NN * 5) return;
    int i = t / 5, q = t % 5;
    float s = g_dinv[i];
    float4 v = *(const float4*)(x + i * FIN + q * 4);
    v.x *= s; v.y *= s; v.z *= s; v.w *= s;
    *(float4*)(g_y20 + i * FIN + q * 4) = v;
}

// a20[d] = y20[d] + sum_{s in adj(d)} y20[s]   (warp per node, lanes 0..19)
__global__ void k_gath20() {
    int t = blockIdx.x * blockDim.x + threadIdx.x;
    int w = t >> 5;
    if (w >= NN) return;
    int lane = t & 31;
    int off = __ldg(g_off + w), deg = __ldg(g_degi + w);
    float acc = (lane < FIN) ? __ldg(g_y20 + (size_t)w * FIN + lane) : 0.f;
    int i = 0;
    for (; i + 4 <= deg; i += 4) {
        int s0 = __ldg(g_adj + off + i);
        int s1 = __ldg(g_adj + off + i + 1);
        int s2 = __ldg(g_adj + off + i + 2);
        int s3 = __ldg(g_adj + off + i + 3);
        if (lane < FIN) {
            float v0 = __ldg(g_y20 + (size_t)s0 * FIN + lane);
            float v1 = __ldg(g_y20 + (size_t)s1 * FIN + lane);
            float v2 = __ldg(g_y20 + (size_t)s2 * FIN + lane);
            float v3 = __ldg(g_y20 + (size_t)s3 * FIN + lane);
            acc += (v0 + v1) + (v2 + v3);
        }
    }
    for (; i < deg; i++) {
        int s = __ldg(g_adj + off + i);
        if (lane < FIN) acc += __ldg(g_y20 + (size_t)s * FIN + lane);
    }
    if (lane < FIN) g_a20[(size_t)w * FIN + lane] = acc;
}

// A[d] = Y[d] + sum_{s in adj(d)} Y[s]   (warp per node, float4 per lane)
__global__ void k_gath128() {
    int t = blockIdx.x * blockDim.x + threadIdx.x;
    int w = t >> 5;
    if (w >= NN) return;
    int lane = t & 31;
    int off = __ldg(g_off + w), deg = __ldg(g_degi + w);
    const float4* Yv = (const float4*)g_Y;
    float4 a = __ldg(Yv + (size_t)w * 32 + lane);   // self loop
    int i = 0;
    for (; i + 4 <= deg; i += 4) {
        int s0 = __ldg(g_adj + off + i);
        int s1 = __ldg(g_adj + off + i + 1);
        int s2 = __ldg(g_adj + off + i + 2);
        int s3 = __ldg(g_adj + off + i + 3);
        float4 v0 = __ldg(Yv + (size_t)s0 * 32 + lane);
        float4 v1 = __ldg(Yv + (size_t)s1 * 32 + lane);
        float4 v2 = __ldg(Yv + (size_t)s2 * 32 + lane);
        float4 v3 = __ldg(Yv + (size_t)s3 * 32 + lane);
        a.x += (v0.x + v1.x) + (v2.x + v3.x);
        a.y += (v0.y + v1.y) + (v2.y + v3.y);
        a.z += (v0.z + v1.z) + (v2.z + v3.z);
        a.w += (v0.w + v1.w) + (v2.w + v3.w);
    }
    for (; i < deg; i++) {
        int s = __ldg(g_adj + off + i);
        float4 v = __ldg(Yv + (size_t)s * 32 + lane);
        a.x += v.x; a.y += v.y; a.z += v.z; a.w += v.w;
    }
    ((float4*)g_A)[(size_t)w * 32 + lane] = a;
}

// ---------------- fused GEMM ----------------
// out_row = relu( (dinv[row] * A[row,:]) @ W + b )
// MODE 0: store out*dinv[row] into g_Y (input to next aggregation)
// MODE 1: red.v4-accumulate out into g_pool[batch[row]]
template <int K, int KC, int KCP, int MODE>
__global__ __launch_bounds__(256) void k_gemm(const float* __restrict__ W,
                                              const float* __restrict__ bias,
                                              const int* __restrict__ batch) {
    const float* A = (K == FIN) ? (const float*)g_a20 : (const float*)g_A;
    __shared__ float Ws[KC * H];
    __shared__ float As[64 * KCP];
    int tid = threadIdx.x;
    int row0 = blockIdx.x * 64;
    int rg = tid >> 4;
    int cg = tid & 15;
    int c0 = cg * 8;

    unsigned long long acc[4][4];
#pragma unroll
    for (int r = 0; r < 4; r++)
#pragma unroll
        for (int j = 0; j < 4; j++) acc[r][j] = 0ull;

    for (int kc = 0; kc < K; kc += KC) {
        for (int t = tid; t < KC * 32; t += 256) {
            int kk = t >> 5, c4 = (t & 31) * 4;
            *(float4*)(Ws + kk * H + c4) = *(const float4*)(W + (size_t)(kc + kk) * H + c4);
        }
        for (int t = tid; t < (64 * KC) / 4; t += 256) {
            int r = t / (KC / 4), q = (t % (KC / 4)) * 4;
            int row = row0 + r;
            float4 v = make_float4(0.f, 0.f, 0.f, 0.f);
            float s = 0.f;
            if (row < NN) {
                v = *(const float4*)(A + (size_t)row * K + kc + q);
                s = g_dinv[row];
            }
            v.x *= s; v.y *= s; v.z *= s; v.w *= s;
            *(float4*)(As + r * KCP + q) = v;
        }
        __syncthreads();
#pragma unroll
        for (int kk = 0; kk < KC; kk++) {
            ulonglong2 w0 = *(const ulonglong2*)(Ws + kk * H + c0);
            ulonglong2 w1 = *(const ulonglong2*)(Ws + kk * H + c0 + 4);
#pragma unroll
            for (int r = 0; r < 4; r++) {
                float a = As[(rg * 4 + r) * KCP + kk];
                unsigned long long aa = pk2(a, a);
                fma2(acc[r][0], aa, w0.x);
                fma2(acc[r][1], aa, w0.y);
                fma2(acc[r][2], aa, w1.x);
                fma2(acc[r][3], aa, w1.y);
            }
        }
        __syncthreads();
    }

    float b[8];
#pragma unroll
    for (int c = 0; c < 8; c++) b[c] = __ldg(bias + c0 + c);

#pragma unroll
    for (int r = 0; r < 4; r++) {
        int row = row0 + rg * 4 + r;
        if (row >= NN) continue;
        float o[8];
#pragma unroll
        for (int j = 0; j < 4; j++) unpk2(acc[r][j], o[2 * j], o[2 * j + 1]);
#pragma unroll
        for (int c = 0; c < 8; c++) o[c] = fmaxf(o[c] + b[c], 0.f);

        if (MODE == 0) {
            float s = g_dinv[row];
            size_t base = (size_t)row * H + c0;
            *(float4*)(g_Y + base) = make_float4(o[0] * s, o[1] * s, o[2] * s, o[3] * s);
            *(float4*)(g_Y + base + 4) = make_float4(o[4] * s, o[5] * s, o[6] * s, o[7] * s);
        } else {
            int g = __ldg(batch + row);
            float* p = g_pool + (size_t)g * H + c0;
            red4(p, o[0], o[1], o[2], o[3]);
            red4(p + 4, o[4], o[5], o[6], o[7]);
        }
    }
}

__global__ void k_final(const float* __restrict__ Wout,
                        const float* __restrict__ bout,
                        float* __restrict__ out) {
    int g = blockIdx.x;
    int c = threadIdx.x;  // 0..63
    float inv = 1.0f / fmaxf(g_cnt[g], 1.0f);
    float acc = 0.f;
#pragma unroll 16
    for (int k = 0; k < H; k++)
        acc += g_pool[g * H + k] * __ldg(Wout + k * FOUT + c);
    out[g * FOUT + c] = acc * inv + bout[c];
}

// ---------------- launch ----------------
extern "C" void kernel_launch(void* const* d_in, const int* in_sizes, int n_in,
                              void* d_out, int out_size) {
    const float* x = (const float*)d_in[0];
    const int* ei = (const int*)d_in[1];
    const int* batch = (const int*)d_in[2];
    const float* W1 = (const float*)d_in[3];
    const float* b1 = (const float*)d_in[4];
    const float* W2 = (const float*)d_in[5];
    const float* b2 = (const float*)d_in[6];
    const float* W3 = (const float*)d_in[7];
    const float* b3 = (const float*)d_in[8];
    const float* Wo = (const float*)d_in[9];
    const float* bo = (const float*)d_in[10];
    float* out = (float*)d_out;

    const int gemm_blocks = (NN + 63) / 64;
    const int warp_blocks = (int)(((size_t)NN * 32 + 255) / 256);

    // CSR build + norms
    k_zero<<<(NN + 255) / 256, 256>>>();
    k_deg<<<(NE + 255) / 256, 256>>>(ei);
    k_cnt<<<(NN + 255) / 256, 256>>>(batch);
    k_scan1<<<NBS, 256>>>();
    k_scan2<<<1, 512>>>();
    k_scan3<<<(NN + 255) / 256, 256>>>();
    k_scatter<<<(NE + 255) / 256, 256>>>(ei);

    // layer 1: aggregate 20-dim input, then GEMM 20->128
    k_init20<<<(NN * 5 + 255) / 256, 256>>>(x);
    k_gath20<<<warp_blocks, 256>>>();
    k_gemm<FIN, 20, 24, 0><<<gemm_blocks, 256>>>(W1, b1, nullptr);

    // layer 2
    k_gath128<<<warp_blocks, 256>>>();
    k_gemm<H, 32, 36, 0><<<gemm_blocks, 256>>>(W2, b2, nullptr);

    // layer 3 (epilogue pools directly)
    k_gath128<<<warp_blocks, 256>>>();
    k_gemm<H, 32, 36, 1><<<gemm_blocks, 256>>>(W3, b3, batch);

    // head
    k_final<<<NG, FOUT>>>(Wo, bo, out);
}

// round 10
// speedup vs baseline: 1.5314x; 1.0044x over previous
#include <cuda_runtime.h>

#define NN 100000
#define NE 1600000
#define NG 512
#define FIN 20
#define H 128
#define FOUT 64
#define NBS ((NN + 255) / 256)   // scan blocks = 391

// ---------------- scratch (static device globals; no allocs) ----------------
__device__ __align__(128) int   g_degi[NN];
__device__ __align__(128) int   g_off[NN];
__device__ __align__(128) int   g_cur[NN];
__device__ __align__(128) int   g_bsum[NBS];
__device__ __align__(128) int   g_bpre[NBS];
__device__ __align__(128) int   g_adj[NE];
__device__ __align__(128) float g_dinv[NN];
__device__ __align__(128) float g_y20[NN * FIN];
__device__ __align__(128) float g_Y[(size_t)NN * H];    // layer-1 output
__device__ __align__(128) float g_Yb[(size_t)NN * H];   // layer-2 output (ping-pong)
__device__ __align__(128) float g_pool[NG * H];
__device__ __align__(128) float g_cnt[NG];

// ---------------- helpers ----------------
__device__ __forceinline__ unsigned long long pk2(float lo, float hi) {
    unsigned long long r;
    asm("mov.b64 %0,{%1,%2};" : "=l"(r) : "f"(lo), "f"(hi));
    return r;
}
__device__ __forceinline__ void fma2(unsigned long long& d, unsigned long long a, unsigned long long b) {
    asm("fma.rn.f32x2 %0,%1,%2,%0;" : "+l"(d) : "l"(a), "l"(b));
}
__device__ __forceinline__ void unpk2(unsigned long long v, float& lo, float& hi) {
    asm("mov.b64 {%0,%1},%2;" : "=f"(lo), "=f"(hi) : "l"(v));
}
__device__ __forceinline__ void red4(float* p, float a, float b, float c, float d) {
    asm volatile("red.global.add.v4.f32 [%0],{%1,%2,%3,%4};"
                 :: "l"(p), "f"(a), "f"(b), "f"(c), "f"(d) : "memory");
}

// ---------------- setup kernels ----------------
__global__ void k_zero() {
    int i = blockIdx.x * blockDim.x + threadIdx.x;
    if (i < NN) { g_degi[i] = 0; g_cur[i] = 0; }
    if (i < NG * H) g_pool[i] = 0.f;
    if (i < NG) g_cnt[i] = 0.f;
}

__global__ void k_deg(const int* __restrict__ ei) {
    int e = blockIdx.x * blockDim.x + threadIdx.x;
    if (e < NE) atomicAdd(&g_degi[__ldg(ei + NE + e)], 1);
}

// smem-aggregated graph-size histogram (batch is sorted -> few bins per block)
__global__ void k_cnt(const int* __restrict__ batch) {
    __shared__ float h[NG];
    for (int g = threadIdx.x; g < NG; g += 256) h[g] = 0.f;
    __syncthreads();
    int i = blockIdx.x * blockDim.x + threadIdx.x;
    if (i < NN) atomicAdd(&h[__ldg(batch + i)], 1.0f);
    __syncthreads();
    for (int g = threadIdx.x; g < NG; g += 256)
        if (h[g] != 0.f) atomicAdd(&g_cnt[g], h[g]);
}

// ---------------- exclusive scan of g_degi -> g_off ----------------
__global__ void k_scan1() {
    __shared__ int s[2][256];
    int t = threadIdx.x, b = blockIdx.x;
    int i = b * 256 + t;
    int v = (i < NN) ? g_degi[i] : 0;
    int cur = 0;
    s[0][t] = v;
    __syncthreads();
#pragma unroll
    for (int o = 1; o < 256; o <<= 1) {
        int nv = s[cur][t] + (t >= o ? s[cur][t - o] : 0);
        s[cur ^ 1][t] = nv;
        __syncthreads();
        cur ^= 1;
    }
    int inc = s[cur][t];
    if (i < NN) g_off[i] = inc - v;
    if (t == 255) g_bsum[b] = inc;
}

__global__ void k_scan2() {
    __shared__ int s[2][512];
    int t = threadIdx.x;
    int v = (t < NBS) ? g_bsum[t] : 0;
    int cur = 0;
    s[0][t] = v;
    __syncthreads();
#pragma unroll
    for (int o = 1; o < 512; o <<= 1) {
        int nv = s[cur][t] + (t >= o ? s[cur][t - o] : 0);
        s[cur ^ 1][t] = nv;
        __syncthreads();
        cur ^= 1;
    }
    if (t < NBS) g_bpre[t] = s[cur][t] - v;
}

// finalize offsets, compute dinv, and write y20 = x * dinv  (init20 fused)
__global__ void k_scan3(const float* __restrict__ x) {
    int i = blockIdx.x * blockDim.x + threadIdx.x;
    if (i >= NN) return;
    g_off[i] += g_bpre[i >> 8];
    float s = rsqrtf((float)g_degi[i] + 1.0f);  // +1 = self loop
    g_dinv[i] = s;
#pragma unroll
    for (int q = 0; q < 5; q++) {
        float4 v = *(const float4*)(x + (size_t)i * FIN + q * 4);
        v.x *= s; v.y *= s; v.z *= s; v.w *= s;
        *(float4*)(g_y20 + (size_t)i * FIN + q * 4) = v;
    }
}

// fill CSR adjacency: g_adj[off[d] .. off[d]+deg[d]) = src of edges into d
__global__ void k_scatter(const int* __restrict__ ei) {
    int e = blockIdx.x * blockDim.x + threadIdx.x;
    if (e >= NE) return;
    int s = __ldg(ei + e);
    int d = __ldg(ei + NE + e);
    int pos = g_off[d] + atomicAdd(&g_cur[d], 1);
    g_adj[pos] = s;
}

// ---------------- fused gather + GEMM ----------------
// Block handles 64 rows. Phase 1: warp-per-node CSR gather of the normalized
// aggregate dinv[d]*(Yin[d] + sum Yin[src]) directly into smem As.
// Phase 2: register-tiled f32x2 GEMM: out = relu(As @ W + b).
// MODE 0: Yout[row] = out * dinv[row]   MODE 1: pool[batch[row]] += out
// K == FIN: Yin is g_y20 (scalar lanes), else a [NN,H] buffer (float4 lanes).
// RACE NOTE: Yin and Yout MUST be distinct arrays (ping-pong) — phase 1 reads
// arbitrary rows of Yin while other blocks' phase 2 writes Yout.
template <int K, int KCP, int KC, int MODE>
__global__ __launch_bounds__(256) void k_fused(const float* __restrict__ Yin,
                                               float* __restrict__ Yout,
                                               const float* __restrict__ W,
                                               const float* __restrict__ bias,
                                               const int* __restrict__ batch) {
    __shared__ float As[64 * KCP];
    __shared__ float Ws[KC * H];
    int tid = threadIdx.x;
    int row0 = blockIdx.x * 64;
    int wid = tid >> 5, lane = tid & 31;

    // ---- phase 1: gather into As (scaled by dinv) ----
    for (int n = wid; n < 64; n += 8) {
        int row = row0 + n;
        if (row >= NN) continue;
        int off = __ldg(g_off + row), deg = __ldg(g_degi + row);
        float s = __ldg(g_dinv + row);
        if (K == FIN) {
            float acc = (lane < FIN) ? __ldg(Yin + (size_t)row * FIN + lane) : 0.f;
            int i = 0;
            for (; i + 4 <= deg; i += 4) {
                int s0 = __ldg(g_adj + off + i);
                int s1 = __ldg(g_adj + off + i + 1);
                int s2 = __ldg(g_adj + off + i + 2);
                int s3 = __ldg(g_adj + off + i + 3);
                if (lane < FIN) {
                    float v0 = __ldg(Yin + (size_t)s0 * FIN + lane);
                    float v1 = __ldg(Yin + (size_t)s1 * FIN + lane);
                    float v2 = __ldg(Yin + (size_t)s2 * FIN + lane);
                    float v3 = __ldg(Yin + (size_t)s3 * FIN + lane);
                    acc += (v0 + v1) + (v2 + v3);
                }
            }
            for (; i < deg; i++) {
                int sx = __ldg(g_adj + off + i);
                if (lane < FIN) acc += __ldg(Yin + (size_t)sx * FIN + lane);
            }
            if (lane < FIN) As[n * KCP + lane] = acc * s;
        } else {
            const float4* Yv = (const float4*)Yin;
            float4 a = __ldg(Yv + (size_t)row * 32 + lane);   // self loop
            int i = 0;
            for (; i + 4 <= deg; i += 4) {
                int s0 = __ldg(g_adj + off + i);
                int s1 = __ldg(g_adj + off + i + 1);
                int s2 = __ldg(g_adj + off + i + 2);
                int s3 = __ldg(g_adj + off + i + 3);
                float4 v0 = __ldg(Yv + (size_t)s0 * 32 + lane);
                float4 v1 = __ldg(Yv + (size_t)s1 * 32 + lane);
                float4 v2 = __ldg(Yv + (size_t)s2 * 32 + lane);
                float4 v3 = __ldg(Yv + (size_t)s3 * 32 + lane);
                a.x += (v0.x + v1.x) + (v2.x + v3.x);
                a.y += (v0.y + v1.y) + (v2.y + v3.y);
                a.z += (v0.z + v1.z) + (v2.z + v3.z);
                a.w += (v0.w + v1.w) + (v2.w + v3.w);
            }
            for (; i < deg; i++) {
                int sx = __ldg(g_adj + off + i);
                float4 v = __ldg(Yv + (size_t)sx * 32 + lane);
                a.x += v.x; a.y += v.y; a.z += v.z; a.w += v.w;
            }
            a.x *= s; a.y *= s; a.z *= s; a.w *= s;
            *(float4*)(As + n * KCP + lane * 4) = a;
        }
    }
    __syncthreads();

    // ---- phase 2: GEMM ----
    int rg = tid >> 4;        // 0..15 -> rows rg*4..rg*4+3
    int cg = tid & 15;        // cols cg*8..cg*8+7
    int c0 = cg * 8;

    unsigned long long acc[4][4];
#pragma unroll
    for (int r = 0; r < 4; r++)
#pragma unroll
        for (int j = 0; j < 4; j++) acc[r][j] = 0ull;

    for (int kc = 0; kc < K; kc += KC) {
        for (int t = tid; t < KC * 32; t += 256) {
            int kk = t >> 5, c4 = (t & 31) * 4;
            *(float4*)(Ws + kk * H + c4) = *(const float4*)(W + (size_t)(kc + kk) * H + c4);
        }
        __syncthreads();
#pragma unroll
        for (int kk = 0; kk < KC; kk++) {
            ulonglong2 w0 = *(const ulonglong2*)(Ws + kk * H + c0);
            ulonglong2 w1 = *(const ulonglong2*)(Ws + kk * H + c0 + 4);
#pragma unroll
            for (int r = 0; r < 4; r++) {
                float a = As[(rg * 4 + r) * KCP + kc + kk];
                unsigned long long aa = pk2(a, a);
                fma2(acc[r][0], aa, w0.x);
                fma2(acc[r][1], aa, w0.y);
                fma2(acc[r][2], aa, w1.x);
                fma2(acc[r][3], aa, w1.y);
            }
        }
        __syncthreads();
    }

    float b[8];
#pragma unroll
    for (int c = 0; c < 8; c++) b[c] = __ldg(bias + c0 + c);

#pragma unroll
    for (int r = 0; r < 4; r++) {
        int row = row0 + rg * 4 + r;
        if (row >= NN) continue;
        float o[8];
#pragma unroll
        for (int j = 0; j < 4; j++) unpk2(acc[r][j], o[2 * j], o[2 * j + 1]);
#pragma unroll
        for (int c = 0; c < 8; c++) o[c] = fmaxf(o[c] + b[c], 0.f);

        if (MODE == 0) {
            float s = __ldg(g_dinv + row);
            size_t base = (size_t)row * H + c0;
            *(float4*)(Yout + base) = make_float4(o[0] * s, o[1] * s, o[2] * s, o[3] * s);
            *(float4*)(Yout + base + 4) = make_float4(o[4] * s, o[5] * s, o[6] * s, o[7] * s);
        } else {
            int g = __ldg(batch + row);
            float* p = g_pool + (size_t)g * H + c0;
            red4(p, o[0], o[1], o[2], o[3]);
            red4(p + 4, o[4], o[5], o[6], o[7]);
        }
    }
}

__global__ void k_final(const float* __restrict__ Wout,
                        const float* __restrict__ bout,
                        float* __restrict__ out) {
    int g = blockIdx.x;
    int c = threadIdx.x;  // 0..63
    float inv = 1.0f / fmaxf(g_cnt[g], 1.0f);
    float acc = 0.f;
#pragma unroll 16
    for (int k = 0; k < H; k++)
        acc += g_pool[g * H + k] * __ldg(Wout + k * FOUT + c);
    out[g * FOUT + c] = acc * inv + bout[c];
}

// ---------------- launch ----------------
extern "C" void kernel_launch(void* const* d_in, const int* in_sizes, int n_in,
                              void* d_out, int out_size) {
    const float* x = (const float*)d_in[0];
    const int* ei = (const int*)d_in[1];
    const int* batch = (const int*)d_in[2];
    const float* W1 = (const float*)d_in[3];
    const float* b1 = (const float*)d_in[4];
    const float* W2 = (const float*)d_in[5];
    const float* b2 = (const float*)d_in[6];
    const float* W3 = (const float*)d_in[7];
    const float* b3 = (const float*)d_in[8];
    const float* Wo = (const float*)d_in[9];
    const float* bo = (const float*)d_in[10];
    float* out = (float*)d_out;

    const int blocks64 = (NN + 63) / 64;

    // device-global addresses for ping-pong buffers
    float *pY, *pYb, *py20;
    cudaGetSymbolAddress((void**)&pY, g_Y);
    cudaGetSymbolAddress((void**)&pYb, g_Yb);
    cudaGetSymbolAddress((void**)&py20, g_y20);

    // CSR build + norms + layer-1 feature prep
    k_zero<<<(NN + 255) / 256, 256>>>();
    k_deg<<<(NE + 255) / 256, 256>>>(ei);
    k_cnt<<<(NN + 255) / 256, 256>>>(batch);
    k_scan1<<<NBS, 256>>>();
    k_scan2<<<1, 512>>>();
    k_scan3<<<(NN + 255) / 256, 256>>>(x);
    k_scatter<<<(NE + 255) / 256, 256>>>(ei);

    // layer 1: fused gather(20) + GEMM 20->128   (y20 -> Y)
    k_fused<FIN, 25, FIN, 0><<<blocks64, 256>>>(py20, pY, W1, b1, nullptr);
    // layer 2: fused gather(128) + GEMM 128->128 (Y -> Yb)
    k_fused<H, 132, 16, 0><<<blocks64, 256>>>(pY, pYb, W2, b2, nullptr);
    // layer 3: fused gather(128) + GEMM 128->128, epilogue pools (Yb -> pool)
    k_fused<H, 132, 16, 1><<<blocks64, 256>>>(pYb, nullptr, W3, b3, batch);

    // head
    k_final<<<NG, FOUT>>>(Wo, bo, out);
}

// round 13
// speedup vs baseline: 1.6405x; 1.0712x over previous
#include <cuda_runtime.h>
#include <cuda_bf16.h>

#define NN 100000
#define NE 1600000
#define NG 512
#define FIN 20
#define H 128
#define FOUT 64
#define NBS ((NN + 255) / 256)   // scan blocks = 391

// ---------------- scratch (static device globals; no allocs) ----------------
__device__ __align__(128) int   g_degi[NN];
__device__ __align__(128) int   g_off[NN];
__device__ __align__(128) int   g_cur[NN];
__device__ __align__(128) int   g_bsum[NBS];
__device__ __align__(128) int   g_bpre[NBS];
__device__ __align__(128) int   g_adj[NE];
__device__ __align__(128) float g_dinv[NN];
__device__ __align__(128) float g_y20[NN * FIN];
__device__ __align__(128) __nv_bfloat16 g_Y[(size_t)NN * H];    // layer-1 output (bf16)
__device__ __align__(128) __nv_bfloat16 g_Yb[(size_t)NN * H];   // layer-2 output (bf16)
__device__ __align__(128) float g_pool[NG * H];
__device__ __align__(128) float g_cnt[NG];

// ---------------- helpers ----------------
__device__ __forceinline__ unsigned long long pk2(float lo, float hi) {
    unsigned long long r;
    asm("mov.b64 %0,{%1,%2};" : "=l"(r) : "f"(lo), "f"(hi));
    return r;
}
__device__ __forceinline__ void fma2(unsigned long long& d, unsigned long long a, unsigned long long b) {
    asm("fma.rn.f32x2 %0,%1,%2,%0;" : "+l"(d) : "l"(a), "l"(b));
}
__device__ __forceinline__ void unpk2(unsigned long long v, float& lo, float& hi) {
    asm("mov.b64 {%0,%1},%2;" : "=f"(lo), "=f"(hi) : "l"(v));
}
__device__ __forceinline__ void red4(float* p, float a, float b, float c, float d) {
    asm volatile("red.global.add.v4.f32 [%0],{%1,%2,%3,%4};"
                 :: "l"(p), "f"(a), "f"(b), "f"(c), "f"(d) : "memory");
}
// bf16x2 pair: lower half <- lo, upper half <- hi  (PTX: cvt d, a, b => upper=a, lower=b)
__device__ __forceinline__ unsigned pack_bf2(float lo, float hi) {
    unsigned r;
    asm("cvt.rn.bf16x2.f32 %0, %1, %2;" : "=r"(r) : "f"(hi), "f"(lo));
    return r;
}
// accumulate 4 bf16 (packed in uint2) into 4 fp32
__device__ __forceinline__ void acc_bf4(uint2 v, float& a0, float& a1, float& a2, float& a3) {
    a0 += __uint_as_float(v.x << 16);
    a1 += __uint_as_float(v.x & 0xffff0000u);
    a2 += __uint_as_float(v.y << 16);
    a3 += __uint_as_float(v.y & 0xffff0000u);
}

// ---------------- setup kernels ----------------
__global__ void k_zero() {
    int i = blockIdx.x * blockDim.x + threadIdx.x;
    if (i < NN) { g_degi[i] = 0; g_cur[i] = 0; }
    if (i < NG * H) g_pool[i] = 0.f;
    if (i < NG) g_cnt[i] = 0.f;
}

__global__ void k_deg(const int* __restrict__ ei) {
    int e = blockIdx.x * blockDim.x + threadIdx.x;
    if (e < NE) atomicAdd(&g_degi[__ldg(ei + NE + e)], 1);
}

__global__ void k_cnt(const int* __restrict__ batch) {
    __shared__ float h[NG];
    for (int g = threadIdx.x; g < NG; g += 256) h[g] = 0.f;
    __syncthreads();
    int i = blockIdx.x * blockDim.x + threadIdx.x;
    if (i < NN) atomicAdd(&h[__ldg(batch + i)], 1.0f);
    __syncthreads();
    for (int g = threadIdx.x; g < NG; g += 256)
        if (h[g] != 0.f) atomicAdd(&g_cnt[g], h[g]);
}

// ---------------- exclusive scan of g_degi -> g_off ----------------
__global__ void k_scan1() {
    __shared__ int s[2][256];
    int t = threadIdx.x, b = blockIdx.x;
    int i = b * 256 + t;
    int v = (i < NN) ? g_degi[i] : 0;
    int cur = 0;
    s[0][t] = v;
    __syncthreads();
#pragma unroll
    for (int o = 1; o < 256; o <<= 1) {
        int nv = s[cur][t] + (t >= o ? s[cur][t - o] : 0);
        s[cur ^ 1][t] = nv;
        __syncthreads();
        cur ^= 1;
    }
    int inc = s[cur][t];
    if (i < NN) g_off[i] = inc - v;
    if (t == 255) g_bsum[b] = inc;
}

__global__ void k_scan2() {
    __shared__ int s[2][512];
    int t = threadIdx.x;
    int v = (t < NBS) ? g_bsum[t] : 0;
    int cur = 0;
    s[0][t] = v;
    __syncthreads();
#pragma unroll
    for (int o = 1; o < 512; o <<= 1) {
        int nv = s[cur][t] + (t >= o ? s[cur][t - o] : 0);
        s[cur ^ 1][t] = nv;
        __syncthreads();
        cur ^= 1;
    }
    if (t < NBS) g_bpre[t] = s[cur][t] - v;
}

// finalize offsets, compute dinv, and write y20 = x * dinv
__global__ void k_scan3(const float* __restrict__ x) {
    int i = blockIdx.x * blockDim.x + threadIdx.x;
    if (i >= NN) return;
    g_off[i] += g_bpre[i >> 8];
    float s = rsqrtf((float)g_degi[i] + 1.0f);  // +1 = self loop
    g_dinv[i] = s;
#pragma unroll
    for (int q = 0; q < 5; q++) {
        float4 v = *(const float4*)(x + (size_t)i * FIN + q * 4);
        v.x *= s; v.y *= s; v.z *= s; v.w *= s;
        *(float4*)(g_y20 + (size_t)i * FIN + q * 4) = v;
    }
}

// fill CSR adjacency
__global__ void k_scatter(const int* __restrict__ ei) {
    int e = blockIdx.x * blockDim.x + threadIdx.x;
    if (e >= NE) return;
    int s = __ldg(ei + e);
    int d = __ldg(ei + NE + e);
    int pos = g_off[d] + atomicAdd(&g_cur[d], 1);
    g_adj[pos] = s;
}

// ---------------- fused gather + GEMM ----------------
// Phase 1: warp-per-node CSR gather of dinv[d]*(Yin[d] + sum Yin[src]) into smem.
// Phase 2: f32x2 register-tiled GEMM: out = relu(As @ W + b).
// MODE 0: Yout[row] = bf16(out * dinv[row]);  MODE 1: pool[batch[row]] += out (fp32)
// K == FIN: Yin = g_y20 fp32;  K == H: Yin = bf16 feature buffer.
// Yin/Yout distinct arrays (ping-pong) — no RW race.
template <int K, int KCP, int KC, int MODE>
__global__ __launch_bounds__(256) void k_fused(const void* __restrict__ Yin_,
                                               __nv_bfloat16* __restrict__ Yout,
                                               const float* __restrict__ W,
                                               const float* __restrict__ bias,
                                               const int* __restrict__ batch) {
    __shared__ float As[64 * KCP];
    __shared__ float Ws[KC * H];
    int tid = threadIdx.x;
    int row0 = blockIdx.x * 64;
    int wid = tid >> 5, lane = tid & 31;

    // ---- phase 1: gather into As (scaled by dinv) ----
    for (int n = wid; n < 64; n += 8) {
        int row = row0 + n;
        if (row >= NN) continue;
        int off = __ldg(g_off + row), deg = __ldg(g_degi + row);
        float s = __ldg(g_dinv + row);
        if (K == FIN) {
            const float* Yin = (const float*)Yin_;
            float acc = (lane < FIN) ? __ldg(Yin + (size_t)row * FIN + lane) : 0.f;
            int i = 0;
            for (; i + 4 <= deg; i += 4) {
                int s0 = __ldg(g_adj + off + i);
                int s1 = __ldg(g_adj + off + i + 1);
                int s2 = __ldg(g_adj + off + i + 2);
                int s3 = __ldg(g_adj + off + i + 3);
                if (lane < FIN) {
                    float v0 = __ldg(Yin + (size_t)s0 * FIN + lane);
                    float v1 = __ldg(Yin + (size_t)s1 * FIN + lane);
                    float v2 = __ldg(Yin + (size_t)s2 * FIN + lane);
                    float v3 = __ldg(Yin + (size_t)s3 * FIN + lane);
                    acc += (v0 + v1) + (v2 + v3);
                }
            }
            for (; i < deg; i++) {
                int sx = __ldg(g_adj + off + i);
                if (lane < FIN) acc += __ldg(Yin + (size_t)sx * FIN + lane);
            }
            if (lane < FIN) As[n * KCP + lane] = acc * s;
        } else {
            // bf16 rows: 128 bf16 = 256B; lane owns cols lane*4..lane*4+3 (8B)
            const uint2* Yv = (const uint2*)Yin_;
            float a0 = 0.f, a1 = 0.f, a2 = 0.f, a3 = 0.f;
            acc_bf4(__ldg(Yv + (size_t)row * 32 + lane), a0, a1, a2, a3);  // self loop
            int i = 0;
            for (; i + 4 <= deg; i += 4) {
                int s0 = __ldg(g_adj + off + i);
                int s1 = __ldg(g_adj + off + i + 1);
                int s2 = __ldg(g_adj + off + i + 2);
                int s3 = __ldg(g_adj + off + i + 3);
                uint2 v0 = __ldg(Yv + (size_t)s0 * 32 + lane);
                uint2 v1 = __ldg(Yv + (size_t)s1 * 32 + lane);
                uint2 v2 = __ldg(Yv + (size_t)s2 * 32 + lane);
                uint2 v3 = __ldg(Yv + (size_t)s3 * 32 + lane);
                acc_bf4(v0, a0, a1, a2, a3);
                acc_bf4(v1, a0, a1, a2, a3);
                acc_bf4(v2, a0, a1, a2, a3);
                acc_bf4(v3, a0, a1, a2, a3);
            }
            for (; i < deg; i++) {
                int sx = __ldg(g_adj + off + i);
                acc_bf4(__ldg(Yv + (size_t)sx * 32 + lane), a0, a1, a2, a3);
            }
            *(float4*)(As + n * KCP + lane * 4) = make_float4(a0 * s, a1 * s, a2 * s, a3 * s);
        }
    }
    __syncthreads();

    // ---- phase 2: GEMM ----
    int rg = tid >> 4;        // rows rg*4..rg*4+3
    int cg = tid & 15;        // cols cg*8..cg*8+7
    int c0 = cg * 8;

    unsigned long long acc[4][4];
#pragma unroll
    for (int r = 0; r < 4; r++)
#pragma unroll
        for (int j = 0; j < 4; j++) acc[r][j] = 0ull;

    for (int kc = 0; kc < K; kc += KC) {
        for (int t = tid; t < KC * 32; t += 256) {
            int kk = t >> 5, c4 = (t & 31) * 4;
            *(float4*)(Ws + kk * H + c4) = *(const float4*)(W + (size_t)(kc + kk) * H + c4);
        }
        __syncthreads();
#pragma unroll
        for (int kk = 0; kk < KC; kk++) {
            ulonglong2 w0 = *(const ulonglong2*)(Ws + kk * H + c0);
            ulonglong2 w1 = *(const ulonglong2*)(Ws + kk * H + c0 + 4);
#pragma unroll
            for (int r = 0; r < 4; r++) {
                float a = As[(rg * 4 + r) * KCP + kc + kk];
                unsigned long long aa = pk2(a, a);
                fma2(acc[r][0], aa, w0.x);
                fma2(acc[r][1], aa, w0.y);
                fma2(acc[r][2], aa, w1.x);
                fma2(acc[r][3], aa, w1.y);
            }
        }
        __syncthreads();
    }

    float b[8];
#pragma unroll
    for (int c = 0; c < 8; c++) b[c] = __ldg(bias + c0 + c);

#pragma unroll
    for (int r = 0; r < 4; r++) {
        int row = row0 + rg * 4 + r;
        if (row >= NN) continue;
        float o[8];
#pragma unroll
        for (int j = 0; j < 4; j++) unpk2(acc[r][j], o[2 * j], o[2 * j + 1]);
#pragma unroll
        for (int c = 0; c < 8; c++) o[c] = fmaxf(o[c] + b[c], 0.f);

        if (MODE == 0) {
            float s = __ldg(g_dinv + row);
            uint4 pk;
            pk.x = pack_bf2(o[0] * s, o[1] * s);
            pk.y = pack_bf2(o[2] * s, o[3] * s);
            pk.z = pack_bf2(o[4] * s, o[5] * s);
            pk.w = pack_bf2(o[6] * s, o[7] * s);
            *(uint4*)(Yout + (size_t)row * H + c0) = pk;   // 8 bf16 = 16B
        } else {
            int g = __ldg(batch + row);
            float* p = g_pool + (size_t)g * H + c0;
            red4(p, o[0], o[1], o[2], o[3]);
            red4(p + 4, o[4], o[5], o[6], o[7]);
        }
    }
}

__global__ void k_final(const float* __restrict__ Wout,
                        const float* __restrict__ bout,
                        float* __restrict__ out) {
    int g = blockIdx.x;
    int c = threadIdx.x;  // 0..63
    float inv = 1.0f / fmaxf(g_cnt[g], 1.0f);
    float acc = 0.f;
#pragma unroll 16
    for (int k = 0; k < H; k++)
        acc += g_pool[g * H + k] * __ldg(Wout + k * FOUT + c);
    out[g * FOUT + c] = acc * inv + bout[c];
}

// ---------------- launch ----------------
extern "C" void kernel_launch(void* const* d_in, const int* in_sizes, int n_in,
                              void* d_out, int out_size) {
    const float* x = (const float*)d_in[0];
    const int* ei = (const int*)d_in[1];
    const int* batch = (const int*)d_in[2];
    const float* W1 = (const float*)d_in[3];
    const float* b1 = (const float*)d_in[4];
    const float* W2 = (const float*)d_in[5];
    const float* b2 = (const float*)d_in[6];
    const float* W3 = (const float*)d_in[7];
    const float* b3 = (const float*)d_in[8];
    const float* Wo = (const float*)d_in[9];
    const float* bo = (const float*)d_in[10];
    float* out = (float*)d_out;

    const int blocks64 = (NN + 63) / 64;

    void *pY, *pYb, *py20;
    cudaGetSymbolAddress(&pY, g_Y);
    cudaGetSymbolAddress(&pYb, g_Yb);
    cudaGetSymbolAddress(&py20, g_y20);

    // CSR build + norms + layer-1 feature prep
    k_zero<<<(NN + 255) / 256, 256>>>();
    k_deg<<<(NE + 255) / 256, 256>>>(ei);
    k_cnt<<<(NN + 255) / 256, 256>>>(batch);
    k_scan1<<<NBS, 256>>>();
    k_scan2<<<1, 512>>>();
    k_scan3<<<(NN + 255) / 256, 256>>>(x);
    k_scatter<<<(NE + 255) / 256, 256>>>(ei);

    // layer 1: gather(20, fp32) + GEMM 20->128   (y20 -> Y bf16)
    k_fused<FIN, 25, FIN, 0><<<blocks64, 256>>>(py20, (__nv_bfloat16*)pY, W1, b1, nullptr);
    // layer 2: gather(128, bf16) + GEMM          (Y -> Yb bf16)
    k_fused<H, 132, 16, 0><<<blocks64, 256>>>(pY, (__nv_bfloat16*)pYb, W2, b2, nullptr);
    // layer 3: gather(128, bf16) + GEMM, pools   (Yb -> pool fp32)
    k_fused<H, 132, 16, 1><<<blocks64, 256>>>(pYb, nullptr, W3, b3, batch);

    // head
    k_final<<<NG, FOUT>>>(Wo, bo, out);
}